// round 16
// baseline (speedup 1.0000x reference)
#include <cuda_runtime.h>
#include <cuda_fp16.h>

#define FULLMASK 0xFFFFFFFFu
constexpr int Bb = 4, Nn = 384, Dd = 64;
constexpr int NR = Bb * Nn;
constexpr int GRAM_BLOCKS = Bb * 12 * 12;   // 576
constexpr int ROW_BLOCKS = NR / 8;          // 192

__device__ float g_y2[NR];
__device__ float g_uself[NR * Dd];
__device__ float g_ci[NR * Dd];    // PRE-HALVED
__device__ float g_P[NR * Dd];     // PRE-HALVED
__device__ __align__(16) __half g_Ph[NR * Dd];   // PRE-HALVED fp16, row-major [row][k]
__device__ float g_gram[(size_t)Bb * Nn * Nn];

__device__ __forceinline__ float wred(float v) {
  #pragma unroll
  for (int o = 16; o > 0; o >>= 1) v += __shfl_xor_sync(FULLMASK, v, o);
  return v;
}
__device__ __forceinline__ float sigm(float x) { return 1.f / (1.f + __expf(-x)); }
__device__ __forceinline__ float silu_(float x) { return x * sigm(x); }
__device__ __forceinline__ float artanh_(float x) {
  x = fminf(x, 1.f - 1e-7f);
  return 0.5f * (log1pf(x) - log1pf(-x));
}
__device__ __forceinline__ float tfa(float x) {
  float y; asm("tanh.approx.f32 %0, %1;" : "=f"(y) : "f"(x)); return y;
}
__device__ __forceinline__ unsigned tanh2u(unsigned x) {
  unsigned y; asm("tanh.approx.f16x2 %0, %1;" : "=r"(y) : "r"(x)); return y;
}
__device__ __forceinline__ unsigned hfma2u(unsigned a, unsigned b, unsigned c) {
  unsigned d;
  asm("fma.rn.f16x2 %0, %1, %2, %3;" : "=r"(d) : "r"(a), "r"(b), "r"(c));
  return d;
}

// ===== k_pre: gram tiles + row precompute (adds g_Ph fp16 output) =====
__global__ __launch_bounds__(256)
void k_pre(const float* __restrict__ x,
           const float* __restrict__ att_w1,
           const float* __restrict__ att_b1)
{
  const int tid = threadIdx.x, w = tid >> 5, lane = tid & 31;

  if (blockIdx.x < GRAM_BLOCKS) {
    __shared__ float xis[32][65], xjs[32][65];
    const int t = blockIdx.x;
    const int b = t / 144, rr = t % 144, it = rr / 12, jt = rr % 12;
    const float* xb = x + (size_t)b * Nn * 64;
    for (int e = tid; e < 2048; e += 256) {
      const int r = e >> 6, c = e & 63;
      xis[r][c] = xb[(size_t)(it * 32 + r) * 64 + c];
      xjs[r][c] = xb[(size_t)(jt * 32 + r) * 64 + c];
    }
    __syncthreads();
    const int jj = lane, i4 = w * 4;
    float a0 = 0.f, a1 = 0.f, a2 = 0.f, a3 = 0.f;
    #pragma unroll 16
    for (int k = 0; k < 64; ++k) {
      const float xv = xjs[jj][k];
      a0 = fmaf(xis[i4 + 0][k], xv, a0);
      a1 = fmaf(xis[i4 + 1][k], xv, a1);
      a2 = fmaf(xis[i4 + 2][k], xv, a2);
      a3 = fmaf(xis[i4 + 3][k], xv, a3);
    }
    float* go = g_gram + ((size_t)(b * Nn) + it * 32 + i4) * Nn + jt * 32 + jj;
    go[0] = a0; go[Nn] = a1; go[2 * Nn] = a2; go[3 * Nn] = a3;
    return;
  }

  __shared__ float xis8[8][64];
  __shared__ float us[8][64];
  const int idx = blockIdx.x - GRAM_BLOCKS;
  const int b = idx / 48, i0 = (idx % 48) * 8;
  const float* xb = x + (size_t)b * Nn * 64;

  for (int t = tid; t < 512; t += 256)
    xis8[t >> 6][t & 63] = xb[(size_t)(i0 + (t >> 6)) * 64 + (t & 63)];
  __syncthreads();

  {
    const int r = w, gi = b * Nn + i0 + r;
    const float a0 = xis8[r][lane], a1 = xis8[r][lane + 32];
    const float x2 = wred(a0 * a0 + a1 * a1);
    const float A = 1.f - 2.f * x2 + x2;
    const float Bc = 1.f - x2;
    const float den = fmaxf(1.f - 2.f * x2 + x2 * x2, 1e-15f);
    const float inv = 1.f / den;
    const float s0 = (A * (-a0) + Bc * a0) * inv;
    const float s1 = (A * (-a1) + Bc * a1) * inv;
    const float sn = fmaxf(sqrtf(wred(s0 * s0 + s1 * s1)), 1e-15f);
    const float fac = fmaxf(Bc, 1e-15f);
    const float g = fac * artanh_(sn) / sn;
    us[r][lane] = g * s0; us[r][lane + 32] = g * s1;
    g_uself[(size_t)gi * 64 + lane] = g * s0;
    g_uself[(size_t)gi * 64 + lane + 32] = g * s1;
    if (!lane) g_y2[gi] = x2;
  }
  __syncthreads();

  {
    const int k = tid & 63, rp = tid >> 6;
    float p0 = 0.f, p1 = 0.f, c0 = att_b1[k], c1v = att_b1[k];
    #pragma unroll 8
    for (int d = 0; d < 64; ++d) {
      const float wa = att_w1[d * 64 + k];
      const float wb = att_w1[(64 + d) * 64 + k];
      p0 = fmaf(xis8[rp][d], wa, p0);
      p1 = fmaf(xis8[rp + 4][d], wa, p1);
      c0 = fmaf(us[rp][d], wb, c0);
      c1v = fmaf(us[rp + 4][d], wb, c1v);
    }
    const int g0 = b * Nn + i0 + rp, g1 = g0 + 4;
    g_P[(size_t)g0 * 64 + k] = 0.5f * p0;
    g_P[(size_t)g1 * 64 + k] = 0.5f * p1;
    g_ci[(size_t)g0 * 64 + k] = 0.5f * c0;
    g_ci[(size_t)g1 * 64 + k] = 0.5f * c1v;
    g_Ph[(size_t)g0 * 64 + k] = __float2half_rn(0.5f * p0);
    g_Ph[(size_t)g1 * 64 + k] = __float2half_rn(0.5f * p1);
  }
}

// ===== k_main: 1 row per 128-thread block, fp16 P from global =====
__global__ __launch_bounds__(128, 12)
void k_main(const float* __restrict__ x,
            const int* __restrict__ mask,
            const float* __restrict__ att_w2,
            const float* __restrict__ att_b2,
            const float* __restrict__ mlp_w1,
            const float* __restrict__ mlp_b1,
            const float* __restrict__ mlp_w2,
            const float* __restrict__ mlp_b2,
            float* __restrict__ out)
{
  __shared__ float wkj[Nn];                 // compact att*c2, per segment base w*96
  __shared__ unsigned short jidx[Nn];       // compact j (global within batch)
  __shared__ __half2 cib2[32], pib2[32], w2b2[32];
  __shared__ int mcnt[4];
  __shared__ float s1p[4];
  __shared__ float sup2[2][64];
  __shared__ float supv[64];
  __shared__ float h1p[2][64];
  __shared__ float hmv[64], otv[64];

  const int tid = threadIdx.x, w = tid >> 5, lane = tid & 31;
  const int gi = blockIdx.x;
  const int b = gi / Nn;

  // pack per-row constants into smem half2 (single pass)
  if (tid < 32) {
    cib2[tid] = __floats2half2_rn(g_ci[(size_t)gi * 64 + 2 * tid],
                                  g_ci[(size_t)gi * 64 + 2 * tid + 1]);
  } else if (tid < 64) {
    const int kp = tid - 32;
    pib2[kp] = __floats2half2_rn(g_P[(size_t)gi * 64 + 2 * kp],
                                 g_P[(size_t)gi * 64 + 2 * kp + 1]);
  } else if (tid < 96) {
    const int kp = tid - 64;
    w2b2[kp] = __floats2half2_rn(att_w2[2 * kp], att_w2[2 * kp + 1]);
  }
  // compaction: warp w owns j-segment [w*96, w*96+96)
  {
    const int* mrow = mask + (size_t)gi * Nn + w * 96;
    int m = 0;
    #pragma unroll
    for (int sub = 0; sub < 3; ++sub) {
      const bool ok = mrow[sub * 32 + lane] != 0;
      const unsigned bal = __ballot_sync(FULLMASK, ok);
      const unsigned pre = bal & ((1u << lane) - 1u);
      if (ok) jidx[w * 96 + m + __popc(pre)] =
                  (unsigned short)(w * 96 + sub * 32 + lane);
      m += __popc(bal);
    }
    if (!lane) mcnt[w] = m;
  }
  __syncthreads();

  const float x2i = g_y2[gi];
  const float omx2 = 1.f - x2i;
  const float fac = fmaxf(omx2, 1e-15f);
  const float b2v = att_b2[0];
  float S1 = 0.f;

  const uint4* cibr = (const uint4*)cib2;   // 8 uint4 = 32 half2
  const uint4* pibr = (const uint4*)pib2;
  const uint4* w2br = (const uint4*)w2b2;
  const float* grow = g_gram + (size_t)gi * Nn;
  const float* y2row = g_y2 + b * Nn;
  const __half* Phb = g_Ph + (size_t)(b * Nn) * 64;

  const int mw = mcnt[w];
  for (int g = 0; g * 32 < mw; ++g) {
    const int idx = g * 32 + lane;
    const bool val = idx < mw;
    const int jj = val ? jidx[w * 96 + idx] : 0;
    float c1 = 0.f, c2 = 0.f;
    if (val) {
      const float xy = grow[jj], y2v = y2row[jj];
      const float A = 1.f - 2.f * xy + y2v;
      const float den = fmaxf(fmaf(x2i, y2v, 1.f - 2.f * xy), 1e-15f);
      const float inv = __frcp_rn(den);
      const float t1 = fmaf(A, x2i, -omx2 * xy);
      const float t2 = fmaf(omx2, y2v, -A * xy);
      float sn = sqrtf(fmaxf(inv * inv * fmaf(A, t1, omx2 * t2), 0.f));
      sn = fminf(fmaxf(sn, 1e-15f), 1.f - 1e-7f);
      const float aos = (sn > 1e-3f)
          ? __fdividef(0.5f * __logf((1.f + sn) * __frcp_rn(1.f - sn)), sn)
          : fmaf(sn * sn, 0.33333334f, 1.f);
      const float gg = fac * aos * inv;
      c1 = -gg * A; c2 = gg * omx2;
    }
    const __half2 c1h2 = __float2half2_rn(c1);
    const __half2 c2h2 = __float2half2_rn(c2);
    const unsigned c1u = *(const unsigned*)&c1h2;
    const unsigned c2u = *(const unsigned*)&c2h2;
    const uint4* prow = (const uint4*)(Phb + (size_t)jj * 64);   // 8 uint4 / row
    unsigned a0u = 0, a1u = 0, a2u = 0, a3u = 0;
    #pragma unroll 1
    for (int it = 0; it < 8; ++it) {
      const uint4 pj = prow[it];             // LDG.128, L1-hot (shared by batch)
      const uint4 ci = cibr[it];
      const uint4 pi = pibr[it];
      const uint4 w2 = w2br[it];
      {
        const unsigned t2 = hfma2u(c2u, pj.x, hfma2u(c1u, pi.x, ci.x));
        a0u = hfma2u(hfma2u(t2, tanh2u(t2), t2), w2.x, a0u);
      }
      {
        const unsigned t2 = hfma2u(c2u, pj.y, hfma2u(c1u, pi.y, ci.y));
        a1u = hfma2u(hfma2u(t2, tanh2u(t2), t2), w2.y, a1u);
      }
      {
        const unsigned t2 = hfma2u(c2u, pj.z, hfma2u(c1u, pi.z, ci.z));
        a2u = hfma2u(hfma2u(t2, tanh2u(t2), t2), w2.z, a2u);
      }
      {
        const unsigned t2 = hfma2u(c2u, pj.w, hfma2u(c1u, pi.w, ci.w));
        a3u = hfma2u(hfma2u(t2, tanh2u(t2), t2), w2.w, a3u);
      }
    }
    const float2 f0 = __half22float2(*(const __half2*)&a0u);
    const float2 f1 = __half22float2(*(const __half2*)&a1u);
    const float2 f2 = __half22float2(*(const __half2*)&a2u);
    const float2 f3 = __half22float2(*(const __half2*)&a3u);
    const float pr = ((f0.x + f0.y) + (f1.x + f1.y))
                   + ((f2.x + f2.y) + (f3.x + f3.y));
    const float att = fmaf(0.5f, tfa(0.5f * (pr + b2v)), 0.5f);
    S1 = fmaf(att, c1, S1);
    if (val) wkj[w * 96 + idx] = att * c2;
  }
  {
    const float s = wred(S1);
    if (!lane) s1p[w] = s;
  }
  __syncthreads();

  // support gather: 128 threads = (half, d)
  {
    const int d = tid & 63, half = tid >> 6;
    const float* xb = x + (size_t)(b * Nn) * 64;
    float a0 = 0.f, a1 = 0.f;
    #pragma unroll
    for (int seg = 0; seg < 4; ++seg) {
      const int mt = mcnt[seg];
      const float* wk = wkj + seg * 96;
      const unsigned short* ji = jidx + seg * 96;
      int p = half;
      for (; p + 2 < mt; p += 4) {
        a0 = fmaf(wk[p],     xb[(size_t)ji[p]     * 64 + d], a0);
        a1 = fmaf(wk[p + 2], xb[(size_t)ji[p + 2] * 64 + d], a1);
      }
      for (; p < mt; p += 2)
        a0 = fmaf(wk[p], xb[(size_t)ji[p] * 64 + d], a0);
    }
    sup2[half][d] = a0 + a1;
  }
  __syncthreads();
  if (tid < 64) {
    const float S1t = (s1p[0] + s1p[1]) + (s1p[2] + s1p[3]);
    supv[tid] = fmaf(S1t, x[(size_t)gi * 64 + tid], sup2[0][tid] + sup2[1][tid]);
  }
  __syncthreads();

  // MLP layer1 split: half0 = uself part (+bias), half1 = support part
  {
    const int k = tid & 63, half = tid >> 6;
    float acc;
    if (half == 0) {
      acc = mlp_b1[k];
      #pragma unroll 8
      for (int d = 0; d < 64; ++d)
        acc = fmaf(g_uself[(size_t)gi * 64 + d], mlp_w1[d * 64 + k], acc);
    } else {
      acc = 0.f;
      #pragma unroll 8
      for (int d = 0; d < 64; ++d)
        acc = fmaf(supv[d], mlp_w1[(64 + d) * 64 + k], acc);
    }
    h1p[half][k] = acc;
  }
  __syncthreads();
  if (tid < 64) hmv[tid] = silu_(h1p[0][tid] + h1p[1][tid]);
  __syncthreads();
  if (tid < 64) {
    float o = mlp_b2[tid] + g_uself[(size_t)gi * 64 + tid];
    #pragma unroll 8
    for (int d = 0; d < 64; ++d)
      o = fmaf(hmv[d], mlp_w2[d * 64 + tid], o);
    otv[tid] = o;
  }
  __syncthreads();

  // expmap + proj: warp 0
  if (w == 0) {
    const float a0 = x[(size_t)gi * 64 + lane], a1 = x[(size_t)gi * 64 + lane + 32];
    const float o0 = otv[lane], o1 = otv[lane + 32];
    const float un = fmaxf(sqrtf(wred(o0 * o0 + o1 * o1)), 1e-15f);
    const float lam = 2.f / fmaxf(1.f - x2i, 1e-15f);
    const float th = tanhf(0.5f * lam * un);
    const float sc = th / un;
    const float sec0 = sc * o0, sec1 = sc * o1;
    const float xy = wred(a0 * sec0 + a1 * sec1);
    const float y2 = wred(sec0 * sec0 + sec1 * sec1);
    const float A = 1.f + 2.f * xy + y2;
    const float Bc = 1.f - x2i;
    const float den = fmaxf(1.f + 2.f * xy + x2i * y2, 1e-15f);
    const float inv = 1.f / den;
    float r0 = (A * a0 + Bc * sec0) * inv;
    float r1 = (A * a1 + Bc * sec1) * inv;
    const float nrm = fmaxf(sqrtf(wred(r0 * r0 + r1 * r1)), 1e-15f);
    if (nrm > 0.996f) { const float s = 0.996f / nrm; r0 *= s; r1 *= s; }
    float* orow = out + (size_t)gi * 64;
    orow[lane] = r0; orow[lane + 32] = r1;
  }
}

extern "C" void kernel_launch(void* const* d_in, const int* in_sizes, int n_in,
                              void* d_out, int out_size)
{
  const float* x      = (const float*)d_in[0];
  const int*   mask   = (const int*)d_in[1];
  const float* att_w1 = (const float*)d_in[2];
  const float* att_b1 = (const float*)d_in[3];
  const float* att_w2 = (const float*)d_in[4];
  const float* att_b2 = (const float*)d_in[5];
  const float* mlp_w1 = (const float*)d_in[6];
  const float* mlp_b1 = (const float*)d_in[7];
  const float* mlp_w2 = (const float*)d_in[8];
  const float* mlp_b2 = (const float*)d_in[9];
  float* out = (float*)d_out;

  k_pre<<<GRAM_BLOCKS + ROW_BLOCKS, 256>>>(x, att_w1, att_b1);
  k_main<<<NR, 128>>>(x, mask, att_w2, att_b2,
                      mlp_w1, mlp_b1, mlp_w2, mlp_b2, out);
}